// round 3
// baseline (speedup 1.0000x reference)
#include <cuda_runtime.h>
#include <cstdint>
#include <math.h>

#define T_STEPS 512
#define BATCH   256
#define IN_DIMV 129
#define HID     768
#define OUTD    128
#define KDIM    897           // HID + IN_DIMV
#define NCTA    128
#define UPC     6             // hidden units per CTA (128*6 = 768)
#define GROWS   24            // gate rows per CTA (4 gates * 6 units)
#define WSTR    929           // padded weight stride (odd -> no bank conflicts)
#define KTILE   32
#define NKT     29            // ceil(897/32)
#define DEC_T   256           // decoded timesteps (second half)

// ---------------- static device scratch (no allocations allowed) -------------
__device__ float    g_xT[(size_t)T_STEPS * IN_DIMV * BATCH];   // [t][d][b]
__device__ float    g_hbuf0[HID * BATCH];                      // [k][b]
__device__ float    g_hbuf1[HID * BATCH];
__device__ float    g_hist[(size_t)DEC_T * HID * BATCH];       // [t'][k][b]
__device__ float    g_WdecT[HID * OUTD];                       // [k][o]
__device__ unsigned g_barcnt;
__device__ unsigned g_bargen;

// ---------------- grid barrier (all 128 CTAs resident: 1 CTA/SM) -------------
__device__ __forceinline__ void gridbar() {
    __syncthreads();
    if (threadIdx.x == 0) {
        __threadfence();
        unsigned gen = *(volatile unsigned*)&g_bargen;
        if (atomicAdd(&g_barcnt, 1u) == NCTA - 1u) {
            atomicExch(&g_barcnt, 0u);
            __threadfence();
            atomicAdd(&g_bargen, 1u);
        } else {
            while (*(volatile unsigned*)&g_bargen == gen) { }
        }
        __threadfence();
    }
    __syncthreads();
}

// ---------------- prep kernels ----------------------------------------------
__global__ void zero_h_kernel() {
    int i = blockIdx.x * blockDim.x + threadIdx.x;
    if (i < HID * BATCH) { g_hbuf0[i] = 0.f; g_hbuf1[i] = 0.f; }
}

// seq[t][b][d] -> xT[t][d][b]
__global__ void transpose_x_kernel(const float* __restrict__ seq) {
    __shared__ float tile[32][33];
    int t = blockIdx.z;
    int d0 = blockIdx.x * 32, b0 = blockIdx.y * 32;
    int tx = threadIdx.x, ty = threadIdx.y;
    #pragma unroll
    for (int i = 0; i < 32; i += 8) {
        int d = d0 + tx, b = b0 + ty + i;
        tile[ty + i][tx] = (d < IN_DIMV) ? seq[((size_t)t * BATCH + b) * IN_DIMV + d] : 0.f;
    }
    __syncthreads();
    #pragma unroll
    for (int i = 0; i < 32; i += 8) {
        int d = d0 + ty + i, b = b0 + tx;
        if (d < IN_DIMV)
            g_xT[((size_t)t * IN_DIMV + d) * BATCH + b] = tile[tx][ty + i];
    }
}

// Wdec[o][k] -> WdecT[k][o]
__global__ void transpose_wdec_kernel(const float* __restrict__ Wdec) {
    __shared__ float tile[32][33];
    int k0 = blockIdx.x * 32, o0 = blockIdx.y * 32;
    int tx = threadIdx.x, ty = threadIdx.y;
    #pragma unroll
    for (int i = 0; i < 32; i += 8)
        tile[ty + i][tx] = Wdec[(size_t)(o0 + ty + i) * HID + k0 + tx];
    __syncthreads();
    #pragma unroll
    for (int i = 0; i < 32; i += 8)
        g_WdecT[(size_t)(k0 + ty + i) * OUTD + o0 + tx] = tile[tx][ty + i];
}

// ---------------- persistent fused LSTM kernel -------------------------------
// SMEM: ws[GROWS*WSTR] | hxs[KTILE*BATCH] | gates[GROWS*BATCH] | cs[UPC*BATCH] | bias[32]
#define SMEM_FLOATS (GROWS * WSTR + KTILE * BATCH + GROWS * BATCH + UPC * BATCH + 32)
#define SMEM_MAIN   (SMEM_FLOATS * 4)

__global__ void __launch_bounds__(256, 1)
lstm_kernel(const float* __restrict__ Wih, const float* __restrict__ Whh,
            const float* __restrict__ bih, const float* __restrict__ bhh) {
    extern __shared__ float sm[];
    float* ws    = sm;                                  // 24 x 929
    float* hxs   = ws + GROWS * WSTR;                   // 32 x 256
    float* gates = hxs + KTILE * BATCH;                 // 24 x 256
    float* cs    = gates + GROWS * BATCH;               // 6 x 256
    float* bias  = cs + UPC * BATCH;                    // 24 (+pad)

    const int tid = threadIdx.x;
    const int cta = blockIdx.x;

    // stage fused weights: row r -> gate type r/6, unit (cta*6 + r%6)
    for (int e = tid; e < GROWS * WSTR; e += 256) {
        int r = e / WSTR, k = e - r * WSTR;
        int gr = (r / UPC) * HID + cta * UPC + (r % UPC);
        float v = 0.f;
        if (k < HID)       v = Whh[(size_t)gr * HID + k];
        else if (k < KDIM) v = Wih[(size_t)gr * IN_DIMV + (k - HID)];
        ws[e] = v;
    }
    if (tid < GROWS) {
        int r = tid;
        int gr = (r / UPC) * HID + cta * UPC + (r % UPC);
        bias[r] = bih[gr] + bhh[gr];
    }
    for (int e = tid; e < UPC * BATCH; e += 256) cs[e] = 0.f;
    __syncthreads();

    const int gid = tid & 7;        // gate-row group (3 rows)
    const int bid = tid >> 3;       // batch group (8 cols)
    const int bb  = bid * 8;
    const int r0  = gid * 3;

    float a[3][8];

    for (int t = 0; t < T_STEPS; t++) {
        const float* hread  = (t & 1) ? g_hbuf1 : g_hbuf0;
        float*       hwrite = (t & 1) ? g_hbuf0 : g_hbuf1;

        #pragma unroll
        for (int q = 0; q < 3; q++) {
            float bv = bias[r0 + q];
            #pragma unroll
            for (int x = 0; x < 8; x++) a[q][x] = bv;
        }

        for (int kt = 0; kt < NKT; kt++) {
            const int k0 = kt * KTILE;
            // stage hx tile [KTILE][BATCH] : h rows then x rows (zero pad past 897)
            #pragma unroll
            for (int i = 0; i < 8; i++) {
                int f4  = i * 256 + tid;
                int row = f4 >> 6;
                int col = (f4 & 63) << 2;
                int k   = k0 + row;
                float4 v = make_float4(0.f, 0.f, 0.f, 0.f);
                if (k < HID)
                    v = *(const float4*)&hread[k * BATCH + col];
                else if (k < KDIM)
                    v = *(const float4*)&g_xT[((size_t)t * IN_DIMV + (k - HID)) * BATCH + col];
                *(float4*)&hxs[row * BATCH + col] = v;
            }
            __syncthreads();

            #pragma unroll 8
            for (int kk = 0; kk < KTILE; kk++) {
                const float4 h0 = *(const float4*)&hxs[kk * BATCH + bb];
                const float4 h1 = *(const float4*)&hxs[kk * BATCH + bb + 4];
                float hv[8] = {h0.x, h0.y, h0.z, h0.w, h1.x, h1.y, h1.z, h1.w};
                #pragma unroll
                for (int q = 0; q < 3; q++) {
                    float w = ws[(r0 + q) * WSTR + k0 + kk];
                    #pragma unroll
                    for (int x = 0; x < 8; x++) a[q][x] += w * hv[x];
                }
            }
            __syncthreads();
        }

        // exchange gate pre-activations through SMEM
        #pragma unroll
        for (int q = 0; q < 3; q++) {
            *(float4*)&gates[(r0 + q) * BATCH + bb]     = make_float4(a[q][0], a[q][1], a[q][2], a[q][3]);
            *(float4*)&gates[(r0 + q) * BATCH + bb + 4] = make_float4(a[q][4], a[q][5], a[q][6], a[q][7]);
        }
        __syncthreads();

        // elementwise update: thread tid handles batch=tid for all 6 owned units
        #pragma unroll
        for (int u = 0; u < UPC; u++) {
            float xi = gates[(u)      * BATCH + tid];
            float xf = gates[(6 + u)  * BATCH + tid];
            float xg = gates[(12 + u) * BATCH + tid];
            float xo = gates[(18 + u) * BATCH + tid];
            float ig = 1.f / (1.f + expf(-xi));
            float fg = 1.f / (1.f + expf(-xf));
            float gg = tanhf(xg);
            float og = 1.f / (1.f + expf(-xo));
            float c  = fg * cs[u * BATCH + tid] + ig * gg;
            cs[u * BATCH + tid] = c;
            float h  = og * tanhf(c);
            int gu = cta * UPC + u;
            hwrite[gu * BATCH + tid] = h;
            if (t >= DEC_T)
                g_hist[(size_t)(t - DEC_T) * (HID * BATCH) + gu * BATCH + tid] = h;
        }
        gridbar();
    }
}

// ---------------- decoder GEMM: out[t][b][o] = hist[t][:,b] . WdecT[:, o] ----
__global__ void __launch_bounds__(256)
decode_kernel(const float* __restrict__ bdec, float* __restrict__ out) {
    __shared__ float wt[KTILE * 32];
    const int og  = blockIdx.x;     // 4 groups of 32 output cols
    const int t   = blockIdx.y;     // 256 timesteps
    const int tid = threadIdx.x;    // batch index

    float acc[32];
    #pragma unroll
    for (int i = 0; i < 32; i++) acc[i] = 0.f;

    for (int kt = 0; kt < HID / KTILE; kt++) {
        const int k0 = kt * KTILE;
        #pragma unroll
        for (int i = 0; i < 4; i++) {
            int e = i * 256 + tid;
            int kk = e >> 5, oo = e & 31;
            wt[e] = g_WdecT[(size_t)(k0 + kk) * OUTD + og * 32 + oo];
        }
        __syncthreads();
        #pragma unroll 8
        for (int kk = 0; kk < KTILE; kk++) {
            float hv = g_hist[((size_t)t * HID + k0 + kk) * BATCH + tid];
            #pragma unroll
            for (int o4 = 0; o4 < 8; o4++) {
                float4 w = *(const float4*)&wt[kk * 32 + o4 * 4];
                acc[o4 * 4 + 0] += hv * w.x;
                acc[o4 * 4 + 1] += hv * w.y;
                acc[o4 * 4 + 2] += hv * w.z;
                acc[o4 * 4 + 3] += hv * w.w;
            }
        }
        __syncthreads();
    }

    size_t ob = ((size_t)t * BATCH + tid) * OUTD + og * 32;
    #pragma unroll
    for (int o4 = 0; o4 < 8; o4++) {
        float4 r;
        r.x = acc[o4 * 4 + 0] + bdec[og * 32 + o4 * 4 + 0];
        r.y = acc[o4 * 4 + 1] + bdec[og * 32 + o4 * 4 + 1];
        r.z = acc[o4 * 4 + 2] + bdec[og * 32 + o4 * 4 + 2];
        r.w = acc[o4 * 4 + 3] + bdec[og * 32 + o4 * 4 + 3];
        *(float4*)&out[ob + o4 * 4] = r;
    }
}

// ---------------- launch -----------------------------------------------------
extern "C" void kernel_launch(void* const* d_in, const int* in_sizes, int n_in,
                              void* d_out, int out_size) {
    const float* seq  = (const float*)d_in[0];
    const float* Wih  = (const float*)d_in[1];
    const float* Whh  = (const float*)d_in[2];
    const float* bih  = (const float*)d_in[3];
    const float* bhh  = (const float*)d_in[4];
    const float* Wdec = (const float*)d_in[5];
    const float* bdec = (const float*)d_in[6];
    float* out = (float*)d_out;

    cudaFuncSetAttribute(lstm_kernel, cudaFuncAttributeMaxDynamicSharedMemorySize, SMEM_MAIN);

    zero_h_kernel<<<(HID * BATCH + 255) / 256, 256>>>();
    dim3 tb(32, 8);
    transpose_x_kernel<<<dim3(5, 8, T_STEPS), tb>>>(seq);
    transpose_wdec_kernel<<<dim3(HID / 32, OUTD / 32), tb>>>(Wdec);
    lstm_kernel<<<NCTA, 256, SMEM_MAIN>>>(Wih, Whh, bih, bhh);
    decode_kernel<<<dim3(4, DEC_T), 256>>>(bdec, out);
}

// round 5
// speedup vs baseline: 4.2025x; 4.2025x over previous
#include <cuda_runtime.h>
#include <cstdint>
#include <math.h>

#define T_STEPS 512
#define BATCH   256
#define IN_DIMV 129
#define HID     768
#define OUTD    128
#define XROWS   160           // padded x rows (29*32 - 768)
#define KW      928
#define NCHK    29
#define NCTA    96            // 48 M-tiles x 2 batch halves
#define DEC_T   256
#define KTILE   32

// ---- smem layout (floats): A0 A1 | B0 B1 | cs ; gates alias offset 0
#define SA_OFF(b) ((b) * 2304)             // 32*72
#define SB_OFF(b) (4608 + (b) * 4352)      // 32*136
#define SCS_OFF   13312
#define GST       136
#define SMEM_FLOATS (13312 + 16 * 128)
#define SMEM_SZ   (SMEM_FLOATS * 4)        // 61440 B

// ---------------- static device scratch ----------------
__device__ __align__(128) float g_Wt[(size_t)KW * 3072];               // [k][perm row] tf32
__device__ __align__(128) float g_xT[(size_t)T_STEPS * XROWS * BATCH]; // [t][k][b] tf32
__device__ __align__(128) float g_hT[2 * HID * BATCH];                 // ping-pong [k][b] tf32
__device__ __align__(128) float g_hist[(size_t)DEC_T * HID * BATCH];   // [t'][k][b] fp32
__device__ float    g_bias[3072];
__device__ float    g_WdecT[HID * OUTD];
__device__ unsigned g_barcnt;
__device__ unsigned g_bargen;

// ---------------- helpers ----------------
__device__ __forceinline__ float tf32r(float x) {
    uint32_t u; asm("cvt.rna.tf32.f32 %0, %1;" : "=r"(u) : "f"(x));
    return __uint_as_float(u);
}
__device__ __forceinline__ void mma8(float* d, const uint32_t* a, const uint32_t* b) {
    asm volatile("mma.sync.aligned.m16n8k8.row.col.f32.tf32.tf32.f32 "
        "{%0,%1,%2,%3}, {%4,%5,%6,%7}, {%8,%9}, {%0,%1,%2,%3};"
        : "+f"(d[0]), "+f"(d[1]), "+f"(d[2]), "+f"(d[3])
        : "r"(a[0]), "r"(a[1]), "r"(a[2]), "r"(a[3]), "r"(b[0]), "r"(b[1]));
}
__device__ __forceinline__ float sigm(float x) {
    return __fdividef(1.f, 1.f + __expf(-x));
}
__device__ __forceinline__ float tanhx(float x) {
    return __fdividef(2.f, 1.f + __expf(-2.f * x)) - 1.f;
}

// ---------------- grid barrier (96 CTAs, all resident at 1/SM) ----------------
__device__ __forceinline__ void gridbar() {
    __syncthreads();
    if (threadIdx.x == 0) {
        __threadfence();
        unsigned gen = *(volatile unsigned*)&g_bargen;
        if (atomicAdd(&g_barcnt, 1u) == NCTA - 1u) {
            atomicExch(&g_barcnt, 0u);
            __threadfence();
            atomicAdd(&g_bargen, 1u);
        } else {
            while (*(volatile unsigned*)&g_bargen == gen) { }
        }
        __threadfence();
    }
    __syncthreads();
}

// ---------------- prep kernels ----------------
// permuted row p: mBlk = p>>6, r = p&63, g = r>>4, u = r&15 -> orig g*768 + mBlk*16 + u
__global__ void prep_w_kernel(const float* __restrict__ Wih, const float* __restrict__ Whh,
                              const float* __restrict__ bih, const float* __restrict__ bhh) {
    int idx = blockIdx.x * blockDim.x + threadIdx.x;
    if (idx < 3072) {
        int mBlk = idx >> 6, r = idx & 63, g = r >> 4, u = r & 15;
        int orig = g * HID + mBlk * 16 + u;
        g_bias[idx] = bih[orig] + bhh[orig];
    }
    for (size_t e = idx; e < (size_t)KW * 3072; e += (size_t)gridDim.x * blockDim.x) {
        int k = (int)(e / 3072), p = (int)(e % 3072);
        int mBlk = p >> 6, r = p & 63, g = r >> 4, u = r & 15;
        int orig = g * HID + mBlk * 16 + u;
        float v = 0.f;
        if (k < HID)                v = Whh[(size_t)orig * HID + k];
        else if (k < HID + IN_DIMV) v = Wih[(size_t)orig * IN_DIMV + (k - HID)];
        g_Wt[e] = tf32r(v);
    }
}
// g_xT[t][d][b] = tf32(seq[t][b][d]), zero pad d>=129
__global__ void prep_x_kernel(const float* __restrict__ seq) {
    for (size_t e = blockIdx.x * blockDim.x + threadIdx.x;
         e < (size_t)T_STEPS * XROWS * BATCH; e += (size_t)gridDim.x * blockDim.x) {
        int b = (int)(e % BATCH);
        int d = (int)((e / BATCH) % XROWS);
        int t = (int)(e / (BATCH * XROWS));
        g_xT[e] = (d < IN_DIMV) ? tf32r(seq[((size_t)t * BATCH + b) * IN_DIMV + d]) : 0.f;
    }
}
__global__ void zero_h_kernel() {
    int i = blockIdx.x * blockDim.x + threadIdx.x;
    if (i < 2 * HID * BATCH) g_hT[i] = 0.f;
}
__global__ void transpose_wdec_kernel(const float* __restrict__ Wdec) {
    __shared__ float tile[32][33];
    int k0 = blockIdx.x * 32, o0 = blockIdx.y * 32;
    int tx = threadIdx.x, ty = threadIdx.y;
    #pragma unroll
    for (int i = 0; i < 32; i += 8)
        tile[ty + i][tx] = Wdec[(size_t)(o0 + ty + i) * HID + k0 + tx];
    __syncthreads();
    #pragma unroll
    for (int i = 0; i < 32; i += 8)
        g_WdecT[(size_t)(k0 + ty + i) * OUTD + o0 + tx] = tile[tx][ty + i];
}

// ---------------- persistent tensor-core LSTM ----------------
__global__ void __launch_bounds__(256, 1) lstm_mma_kernel() {
    extern __shared__ float sm[];
    float* cs = sm + SCS_OFF;

    const int tid = threadIdx.x, lane = tid & 31, wid = tid >> 5;
    const int wm = wid & 1, wn = wid >> 1;           // warp grid 2(M) x 4(N)
    const int cta = blockIdx.x, mIdx = cta >> 1, nIdx = cta & 1;
    const int q = lane >> 2, rlk = lane & 3;

    // per-thread bias for owned accum rows
    float bias_r[2][2];
    #pragma unroll
    for (int mt = 0; mt < 2; mt++) {
        int r0 = mIdx * 64 + wm * 32 + mt * 16 + q;
        bias_r[mt][0] = g_bias[r0];
        bias_r[mt][1] = g_bias[r0 + 8];
    }
    for (int i = tid; i < 16 * 128; i += 256) cs[i] = 0.f;
    __syncthreads();

    // staging index precompute
    const int kkA0 = (0 * 256 + tid) >> 4, mm40 = tid & 15;
    const int kkA1 = (1 * 256 + tid) >> 4;
    int kkB[4], nn4 = tid & 31;
    #pragma unroll
    for (int i = 0; i < 4; i++) kkB[i] = (i * 256 + tid) >> 5;

    for (int t = 0; t < T_STEPS; t++) {
        const int rslot = t & 1, wslot = rslot ^ 1;
        const float* hT = g_hT + rslot * (HID * BATCH);
        const float* xT = g_xT + (size_t)t * (XROWS * BATCH);

        float d[2][4][4];
        #pragma unroll
        for (int mt = 0; mt < 2; mt++)
            #pragma unroll
            for (int nt = 0; nt < 4; nt++)
                #pragma unroll
                for (int j = 0; j < 4; j++) d[mt][nt][j] = 0.f;

        float4 pa0, pa1, pb[4];

        auto ldg_chunk = [&](int c) {
            const float* wsrc = g_Wt + (size_t)c * 32 * 3072 + mIdx * 64;
            pa0 = *(const float4*)(wsrc + (size_t)kkA0 * 3072 + mm40 * 4);
            pa1 = *(const float4*)(wsrc + (size_t)kkA1 * 3072 + mm40 * 4);
            const float* bsrc = (c < 24) ? (hT + c * 32 * BATCH)
                                         : (xT + (c - 24) * 32 * BATCH);
            bsrc += nIdx * 128;
            #pragma unroll
            for (int i = 0; i < 4; i++)
                pb[i] = *(const float4*)(bsrc + kkB[i] * BATCH + nn4 * 4);
        };
        auto sts_chunk = [&](int buf) {
            *(float4*)(sm + SA_OFF(buf) + kkA0 * 72 + mm40 * 4) = pa0;
            *(float4*)(sm + SA_OFF(buf) + kkA1 * 72 + mm40 * 4) = pa1;
            #pragma unroll
            for (int i = 0; i < 4; i++)
                *(float4*)(sm + SB_OFF(buf) + kkB[i] * GST + nn4 * 4) = pb[i];
        };
        auto compute = [&](int buf) {
            const float* A = sm + SA_OFF(buf);
            const float* B = sm + SB_OFF(buf);
            #pragma unroll
            for (int ks = 0; ks < 4; ks++) {
                const int kb = ks * 8;
                uint32_t a[2][4], b[4][2];
                #pragma unroll
                for (int mt = 0; mt < 2; mt++) {
                    const int m0 = wm * 32 + mt * 16 + q;
                    a[mt][0] = __float_as_uint(A[(kb + rlk) * 72 + m0]);
                    a[mt][1] = __float_as_uint(A[(kb + rlk) * 72 + m0 + 8]);
                    a[mt][2] = __float_as_uint(A[(kb + rlk + 4) * 72 + m0]);
                    a[mt][3] = __float_as_uint(A[(kb + rlk + 4) * 72 + m0 + 8]);
                }
                #pragma unroll
                for (int nt = 0; nt < 4; nt++) {
                    const int n0 = wn * 32 + nt * 8 + q;
                    b[nt][0] = __float_as_uint(B[(kb + rlk) * GST + n0]);
                    b[nt][1] = __float_as_uint(B[(kb + rlk + 4) * GST + n0]);
                }
                #pragma unroll
                for (int mt = 0; mt < 2; mt++)
                    #pragma unroll
                    for (int nt = 0; nt < 4; nt++)
                        mma8(d[mt][nt], a[mt], b[nt]);
            }
        };

        // software-pipelined K loop
        ldg_chunk(0);
        sts_chunk(0);
        __syncthreads();
        for (int c = 0; c < NCHK; c++) {
            if (c + 1 < NCHK) ldg_chunk(c + 1);
            compute(c & 1);
            if (c + 1 < NCHK) sts_chunk((c + 1) & 1);
            __syncthreads();
        }

        // epilogue: accum (+bias) -> smem gates [64][GST]
        #pragma unroll
        for (int mt = 0; mt < 2; mt++) {
            const int r0 = wm * 32 + mt * 16 + q;
            #pragma unroll
            for (int nt = 0; nt < 4; nt++) {
                const int col = wn * 32 + nt * 8 + 2 * rlk;
                *(float2*)&sm[r0 * GST + col] =
                    make_float2(d[mt][nt][0] + bias_r[mt][0], d[mt][nt][1] + bias_r[mt][0]);
                *(float2*)&sm[(r0 + 8) * GST + col] =
                    make_float2(d[mt][nt][2] + bias_r[mt][1], d[mt][nt][3] + bias_r[mt][1]);
            }
        }
        __syncthreads();

        // cell update: b = tid&127, each thread 8 units
        {
            const int b = tid & 127, ug = tid >> 7;
            const int gb = nIdx * 128 + b;
            float* hw = g_hT + wslot * (HID * BATCH);
            #pragma unroll
            for (int uu = 0; uu < 8; uu++) {
                const int u = ug * 8 + uu;
                float xi = sm[(u)      * GST + b];
                float xf = sm[(16 + u) * GST + b];
                float xg = sm[(32 + u) * GST + b];
                float xo = sm[(48 + u) * GST + b];
                float ig = sigm(xi), fg = sigm(xf), gg = tanhx(xg), og = sigm(xo);
                float c = fmaf(fg, cs[u * 128 + b], ig * gg);
                cs[u * 128 + b] = c;
                float h = og * tanhx(c);
                const int kg = mIdx * 16 + u;
                if (t >= DEC_T)
                    g_hist[(size_t)(t - DEC_T) * (HID * BATCH) + (size_t)kg * BATCH + gb] = h;
                hw[kg * BATCH + gb] = tf32r(h);
            }
        }
        gridbar();
    }
}

// ---------------- decoder GEMM: out[t][b][o] ----------------
__global__ void __launch_bounds__(256)
decode_kernel(const float* __restrict__ bdec, float* __restrict__ out) {
    __shared__ float wt[KTILE * 32];
    const int og = blockIdx.x, t = blockIdx.y, tid = threadIdx.x;
    float acc[32];
    #pragma unroll
    for (int i = 0; i < 32; i++) acc[i] = 0.f;
    for (int kt = 0; kt < HID / KTILE; kt++) {
        const int k0 = kt * KTILE;
        #pragma unroll
        for (int i = 0; i < 4; i++) {
            int e = i * 256 + tid, kk = e >> 5, oo = e & 31;
            wt[e] = g_WdecT[(size_t)(k0 + kk) * OUTD + og * 32 + oo];
        }
        __syncthreads();
        #pragma unroll 8
        for (int kk = 0; kk < KTILE; kk++) {
            float hv = g_hist[((size_t)t * HID + k0 + kk) * BATCH + tid];
            #pragma unroll
            for (int o4 = 0; o4 < 8; o4++) {
                float4 w = *(const float4*)&wt[kk * 32 + o4 * 4];
                acc[o4 * 4 + 0] += hv * w.x;  acc[o4 * 4 + 1] += hv * w.y;
                acc[o4 * 4 + 2] += hv * w.z;  acc[o4 * 4 + 3] += hv * w.w;
            }
        }
        __syncthreads();
    }
    size_t ob = ((size_t)t * BATCH + tid) * OUTD + og * 32;
    #pragma unroll
    for (int o4 = 0; o4 < 8; o4++) {
        float4 r;
        r.x = acc[o4 * 4 + 0] + bdec[og * 32 + o4 * 4 + 0];
        r.y = acc[o4 * 4 + 1] + bdec[og * 32 + o4 * 4 + 1];
        r.z = acc[o4 * 4 + 2] + bdec[og * 32 + o4 * 4 + 2];
        r.w = acc[o4 * 4 + 3] + bdec[og * 32 + o4 * 4 + 3];
        *(float4*)&out[ob + o4 * 4] = r;
    }
}

// ---------------- launch ----------------
extern "C" void kernel_launch(void* const* d_in, const int* in_sizes, int n_in,
                              void* d_out, int out_size) {
    const float* seq  = (const float*)d_in[0];
    const float* Wih  = (const float*)d_in[1];
    const float* Whh  = (const float*)d_in[2];
    const float* bih  = (const float*)d_in[3];
    const float* bhh  = (const float*)d_in[4];
    const float* Wdec = (const float*)d_in[5];
    const float* bdec = (const float*)d_in[6];
    float* out = (float*)d_out;

    cudaFuncSetAttribute(lstm_mma_kernel, cudaFuncAttributeMaxDynamicSharedMemorySize, SMEM_SZ);

    zero_h_kernel<<<(2 * HID * BATCH + 255) / 256, 256>>>();
    prep_w_kernel<<<512, 256>>>(Wih, Whh, bih, bhh);
    prep_x_kernel<<<1024, 256>>>(seq);
    dim3 tb(32, 8);
    transpose_wdec_kernel<<<dim3(HID / 32, OUTD / 32), tb>>>(Wdec);
    lstm_mma_kernel<<<NCTA, 256, SMEM_SZ>>>();
    decode_kernel<<<dim3(4, DEC_T), 256>>>(bdec, out);
}

// round 6
// speedup vs baseline: 6.5275x; 1.5532x over previous
#include <cuda_runtime.h>
#include <cuda_fp16.h>
#include <cstdint>
#include <math.h>

#define T_STEPS 512
#define BATCH   256
#define IN_DIMV 129
#define HID     768
#define OUTD    128
#define KW      960            // padded fused K: 768 h + 192 x-pad
#define XST     192
#define CHUNK   64
#define NCHK    15
#define NCTA    96             // 48 M-tiles x 2 batch halves
#define DEC_T   256
#define KTILE   32

#define AST 72                 // smem A row stride (halves)
#define BST 72                 // smem B row stride (halves)
#define GST 132                // gates stride (floats)

// smem byte offsets
#define SA(buf) ((buf) * 9216)             // 64*72*2
#define SB(buf) (18432 + (buf) * 18432)    // 128*72*2
#define SGT     55296                      // 64*132*4 = 33792
#define SCS     89088                      // 16*128*4 = 8192
#define SMEM_SZ 97280

// ---------------- static device scratch ----------------
__device__ __align__(128) __half g_Whm[(size_t)3072 * KW];              // [perm row][k]
__device__ __align__(128) __half g_xbk[(size_t)T_STEPS * BATCH * XST];  // [t][b][k]
__device__ __align__(128) __half g_hbk[2 * BATCH * HID];                // ping-pong [b][k]
__device__ __align__(128) float  g_hist[(size_t)DEC_T * HID * BATCH];   // [t'][k][b] fp32
__device__ float    g_bias[3072];
__device__ float    g_WdecT[HID * OUTD];
__device__ unsigned g_barcnt;
__device__ unsigned g_bargen;

// ---------------- helpers ----------------
__device__ __forceinline__ void mma16(float* d, const uint32_t* a, const uint32_t* b) {
    asm volatile("mma.sync.aligned.m16n8k16.row.col.f32.f16.f16.f32 "
        "{%0,%1,%2,%3}, {%4,%5,%6,%7}, {%8,%9}, {%0,%1,%2,%3};"
        : "+f"(d[0]), "+f"(d[1]), "+f"(d[2]), "+f"(d[3])
        : "r"(a[0]), "r"(a[1]), "r"(a[2]), "r"(a[3]), "r"(b[0]), "r"(b[1]));
}
__device__ __forceinline__ float sigm(float x)  { return __fdividef(1.f, 1.f + __expf(-x)); }
__device__ __forceinline__ float tanhx(float x) { return __fdividef(2.f, 1.f + __expf(-2.f * x)) - 1.f; }

// ---------------- grid barrier (96 CTAs, all resident at 1/SM) ----------------
__device__ __forceinline__ void gridbar() {
    __syncthreads();
    if (threadIdx.x == 0) {
        __threadfence();
        unsigned gen = *(volatile unsigned*)&g_bargen;
        if (atomicAdd(&g_barcnt, 1u) == NCTA - 1u) {
            atomicExch(&g_barcnt, 0u);
            __threadfence();
            atomicAdd(&g_bargen, 1u);
        } else {
            while (*(volatile unsigned*)&g_bargen == gen) { }
        }
        __threadfence();
    }
    __syncthreads();
}

// ---------------- prep kernels ----------------
// perm row p: tile = p>>6, r = p&63, g = r>>4, u = r&15 -> orig g*768 + tile*16 + u
__global__ void prep_w_kernel(const float* __restrict__ Wih, const float* __restrict__ Whh,
                              const float* __restrict__ bih, const float* __restrict__ bhh) {
    int idx = blockIdx.x * blockDim.x + threadIdx.x;
    if (idx < 3072) {
        int tile = idx >> 6, r = idx & 63, g = r >> 4, u = r & 15;
        int orig = g * HID + tile * 16 + u;
        g_bias[idx] = bih[orig] + bhh[orig];
    }
    for (size_t e = idx; e < (size_t)3072 * KW; e += (size_t)gridDim.x * blockDim.x) {
        int p = (int)(e / KW), k = (int)(e % KW);
        int tile = p >> 6, r = p & 63, g = r >> 4, u = r & 15;
        int orig = g * HID + tile * 16 + u;
        float v = 0.f;
        if (k < HID)                v = Whh[(size_t)orig * HID + k];
        else if (k < HID + IN_DIMV) v = Wih[(size_t)orig * IN_DIMV + (k - HID)];
        g_Whm[e] = __float2half_rn(v);
    }
}
__global__ void prep_x_kernel(const float* __restrict__ seq) {
    for (size_t e = blockIdx.x * blockDim.x + threadIdx.x;
         e < (size_t)T_STEPS * BATCH * XST; e += (size_t)gridDim.x * blockDim.x) {
        int k = (int)(e % XST);
        size_t tb = e / XST;
        g_xbk[e] = (k < IN_DIMV) ? __float2half_rn(seq[tb * IN_DIMV + k]) : __ushort_as_half(0);
    }
}
__global__ void zero_h_kernel() {
    int i = blockIdx.x * blockDim.x + threadIdx.x;
    if (i < 2 * BATCH * HID) g_hbk[i] = __ushort_as_half(0);
}
__global__ void transpose_wdec_kernel(const float* __restrict__ Wdec) {
    __shared__ float tile[32][33];
    int k0 = blockIdx.x * 32, o0 = blockIdx.y * 32;
    int tx = threadIdx.x, ty = threadIdx.y;
    #pragma unroll
    for (int i = 0; i < 32; i += 8)
        tile[ty + i][tx] = Wdec[(size_t)(o0 + ty + i) * HID + k0 + tx];
    __syncthreads();
    #pragma unroll
    for (int i = 0; i < 32; i += 8)
        g_WdecT[(size_t)(k0 + ty + i) * OUTD + o0 + tx] = tile[tx][ty + i];
}

// ---------------- persistent fp16 tensor-core LSTM ----------------
__global__ void __launch_bounds__(256, 1) lstm_mma_kernel() {
    extern __shared__ char smc[];
    float* gf  = (float*)(smc + SGT);
    float* cs  = (float*)(smc + SCS);

    const int tid = threadIdx.x, lane = tid & 31, wid = tid >> 5;
    const int wm = wid & 1, wn = wid >> 1;             // warp grid 2(M) x 4(N)
    const int cta = blockIdx.x, mIdx = cta >> 1, nIdx = cta & 1;
    const int q = lane >> 2, rlk = lane & 3;

    float bias_r[2][2];
    #pragma unroll
    for (int mt = 0; mt < 2; mt++) {
        int r0 = mIdx * 64 + wm * 32 + mt * 16 + q;
        bias_r[mt][0] = g_bias[r0];
        bias_r[mt][1] = g_bias[r0 + 8];
    }
    for (int i = tid; i < 16 * 128; i += 256) cs[i] = 0.f;
    __syncthreads();

    // staging index precompute
    int rowA[2], segA[2], rowB[4], segB[4];
    #pragma unroll
    for (int i = 0; i < 2; i++) { int s = i * 256 + tid; rowA[i] = s >> 3; segA[i] = s & 7; }
    #pragma unroll
    for (int i = 0; i < 4; i++) { int s = i * 256 + tid; rowB[i] = s >> 3; segB[i] = s & 7; }

    for (int t = 0; t < T_STEPS; t++) {
        const int rslot = t & 1, wslot = rslot ^ 1;

        float d[2][4][4];
        #pragma unroll
        for (int mt = 0; mt < 2; mt++)
            #pragma unroll
            for (int nt = 0; nt < 4; nt++)
                #pragma unroll
                for (int j = 0; j < 4; j++) d[mt][nt][j] = 0.f;

        uint4 pa[2], pb[4];

        auto ldg_chunk = [&](int c) {
            #pragma unroll
            for (int i = 0; i < 2; i++)
                pa[i] = *(const uint4*)(g_Whm + (size_t)(mIdx * 64 + rowA[i]) * KW
                                        + c * CHUNK + segA[i] * 8);
            const __half* bs;
            int bstr;
            if (c < 12) { bs = g_hbk + ((size_t)rslot * BATCH + nIdx * 128) * HID + c * CHUNK; bstr = HID; }
            else        { bs = g_xbk + ((size_t)t * BATCH + nIdx * 128) * XST + (c - 12) * CHUNK; bstr = XST; }
            #pragma unroll
            for (int i = 0; i < 4; i++)
                pb[i] = *(const uint4*)(bs + (size_t)rowB[i] * bstr + segB[i] * 8);
        };
        auto sts_chunk = [&](int buf) {
            __half* A = (__half*)(smc + SA(buf));
            __half* B = (__half*)(smc + SB(buf));
            #pragma unroll
            for (int i = 0; i < 2; i++)
                *(uint4*)(A + rowA[i] * AST + segA[i] * 8) = pa[i];
            #pragma unroll
            for (int i = 0; i < 4; i++)
                *(uint4*)(B + rowB[i] * BST + segB[i] * 8) = pb[i];
        };
        auto compute = [&](int buf) {
            const __half* A = (const __half*)(smc + SA(buf));
            const __half* B = (const __half*)(smc + SB(buf));
            #pragma unroll
            for (int ks = 0; ks < 4; ks++) {
                const int kb = ks * 16;
                uint32_t a[2][4], b[4][2];
                #pragma unroll
                for (int mt = 0; mt < 2; mt++) {
                    const int m0 = wm * 32 + mt * 16 + q;
                    a[mt][0] = *(const uint32_t*)(A + (m0)     * AST + kb + 2 * rlk);
                    a[mt][1] = *(const uint32_t*)(A + (m0 + 8) * AST + kb + 2 * rlk);
                    a[mt][2] = *(const uint32_t*)(A + (m0)     * AST + kb + 2 * rlk + 8);
                    a[mt][3] = *(const uint32_t*)(A + (m0 + 8) * AST + kb + 2 * rlk + 8);
                }
                #pragma unroll
                for (int nt = 0; nt < 4; nt++) {
                    const int n0 = wn * 32 + nt * 8 + q;
                    b[nt][0] = *(const uint32_t*)(B + n0 * BST + kb + 2 * rlk);
                    b[nt][1] = *(const uint32_t*)(B + n0 * BST + kb + 2 * rlk + 8);
                }
                #pragma unroll
                for (int mt = 0; mt < 2; mt++)
                    #pragma unroll
                    for (int nt = 0; nt < 4; nt++)
                        mma16(d[mt][nt], a[mt], b[nt]);
            }
        };

        ldg_chunk(0);
        sts_chunk(0);
        __syncthreads();
        for (int c = 0; c < NCHK; c++) {
            if (c + 1 < NCHK) ldg_chunk(c + 1);
            compute(c & 1);
            if (c + 1 < NCHK) sts_chunk((c + 1) & 1);
            __syncthreads();
        }

        // epilogue: accum (+bias) -> gates smem [64][GST]
        #pragma unroll
        for (int mt = 0; mt < 2; mt++) {
            const int r0 = wm * 32 + mt * 16 + q;
            #pragma unroll
            for (int nt = 0; nt < 4; nt++) {
                const int col = wn * 32 + nt * 8 + 2 * rlk;
                *(float2*)&gf[r0 * GST + col] =
                    make_float2(d[mt][nt][0] + bias_r[mt][0], d[mt][nt][1] + bias_r[mt][0]);
                *(float2*)&gf[(r0 + 8) * GST + col] =
                    make_float2(d[mt][nt][2] + bias_r[mt][1], d[mt][nt][3] + bias_r[mt][1]);
            }
        }
        __syncthreads();

        // cell update: b = tid&127, ug = tid>>7 -> 8 units each
        {
            const int b = tid & 127, ug = tid >> 7;
            const int gb = nIdx * 128 + b;
            uint4 hpack;
            __half2* hp2 = (__half2*)&hpack;
            #pragma unroll
            for (int uu = 0; uu < 8; uu += 2) {
                float hv2[2];
                #pragma unroll
                for (int w = 0; w < 2; w++) {
                    const int u = ug * 8 + uu + w;
                    float xi = gf[(u)      * GST + b];
                    float xf = gf[(16 + u) * GST + b];
                    float xg = gf[(32 + u) * GST + b];
                    float xo = gf[(48 + u) * GST + b];
                    float ig = sigm(xi), fg = sigm(xf), gg = tanhx(xg), og = sigm(xo);
                    float c = fmaf(fg, cs[u * 128 + b], ig * gg);
                    cs[u * 128 + b] = c;
                    float h = og * tanhx(c);
                    hv2[w] = h;
                    if (t >= DEC_T)
                        g_hist[(size_t)(t - DEC_T) * (HID * BATCH)
                               + (size_t)(mIdx * 16 + u) * BATCH + gb] = h;
                }
                hp2[uu >> 1] = __floats2half2_rn(hv2[0], hv2[1]);
            }
            *(uint4*)(g_hbk + ((size_t)wslot * BATCH + gb) * HID + mIdx * 16 + ug * 8) = hpack;
        }
        gridbar();
    }
}

// ---------------- decoder GEMM: out[t][b][o] ----------------
__global__ void __launch_bounds__(256)
decode_kernel(const float* __restrict__ bdec, float* __restrict__ out) {
    __shared__ float wt[KTILE * 32];
    const int og = blockIdx.x, t = blockIdx.y, tid = threadIdx.x;
    float acc[32];
    #pragma unroll
    for (int i = 0; i < 32; i++) acc[i] = 0.f;
    for (int kt = 0; kt < HID / KTILE; kt++) {
        const int k0 = kt * KTILE;
        #pragma unroll
        for (int i = 0; i < 4; i++) {
            int e = i * 256 + tid, kk = e >> 5, oo = e & 31;
            wt[e] = g_WdecT[(size_t)(k0 + kk) * OUTD + og * 32 + oo];
        }
        __syncthreads();
        #pragma unroll 8
        for (int kk = 0; kk < KTILE; kk++) {
            float hv = g_hist[((size_t)t * HID + k0 + kk) * BATCH + tid];
            #pragma unroll
            for (int o4 = 0; o4 < 8; o4++) {
                float4 w = *(const float4*)&wt[kk * 32 + o4 * 4];
                acc[o4 * 4 + 0] += hv * w.x;  acc[o4 * 4 + 1] += hv * w.y;
                acc[o4 * 4 + 2] += hv * w.z;  acc[o4 * 4 + 3] += hv * w.w;
            }
        }
        __syncthreads();
    }
    size_t ob = ((size_t)t * BATCH + tid) * OUTD + og * 32;
    #pragma unroll
    for (int o4 = 0; o4 < 8; o4++) {
        float4 r;
        r.x = acc[o4 * 4 + 0] + bdec[og * 32 + o4 * 4 + 0];
        r.y = acc[o4 * 4 + 1] + bdec[og * 32 + o4 * 4 + 1];
        r.z = acc[o4 * 4 + 2] + bdec[og * 32 + o4 * 4 + 2];
        r.w = acc[o4 * 4 + 3] + bdec[og * 32 + o4 * 4 + 3];
        *(float4*)&out[ob + o4 * 4] = r;
    }
}

// ---------------- launch ----------------
extern "C" void kernel_launch(void* const* d_in, const int* in_sizes, int n_in,
                              void* d_out, int out_size) {
    const float* seq  = (const float*)d_in[0];
    const float* Wih  = (const float*)d_in[1];
    const float* Whh  = (const float*)d_in[2];
    const float* bih  = (const float*)d_in[3];
    const float* bhh  = (const float*)d_in[4];
    const float* Wdec = (const float*)d_in[5];
    const float* bdec = (const float*)d_in[6];
    float* out = (float*)d_out;

    cudaFuncSetAttribute(lstm_mma_kernel, cudaFuncAttributeMaxDynamicSharedMemorySize, SMEM_SZ);

    zero_h_kernel<<<(2 * BATCH * HID + 255) / 256, 256>>>();
    prep_w_kernel<<<512, 256>>>(Wih, Whh, bih, bhh);
    prep_x_kernel<<<2048, 256>>>(seq);
    dim3 tb(32, 8);
    transpose_wdec_kernel<<<dim3(HID / 32, OUTD / 32), tb>>>(Wdec);
    lstm_mma_kernel<<<NCTA, 256, SMEM_SZ>>>();
    decode_kernel<<<dim3(4, DEC_T), 256>>>(bdec, out);
}

// round 7
// speedup vs baseline: 7.4972x; 1.1486x over previous
#include <cuda_runtime.h>
#include <cuda_fp16.h>
#include <cstdint>
#include <math.h>

#define T_STEPS 512
#define BATCH   256
#define IN_DIMV 129
#define HID     768
#define OUTD    128
#define KW      960            // fused K: 768 h + 192 x-pad
#define XST     192
#define CHUNK   64
#define NCHK    15
#define NCTA    96             // 48 gate-row tiles x 2 batch halves
#define DEC_T   256
#define KTILE   32

#define WST 968                // W smem row stride (halves) -> conflict-free
#define AST 72                 // hx smem row stride (halves)
#define NSTG 4

#define SM_W_BYTES  123904     // 64*968*2
#define SM_HX_STAGE 18432      // 128*72*2
#define SMEM_SZ     (SM_W_BYTES + NSTG * SM_HX_STAGE)   // 197632

// ---------------- static device scratch ----------------
__device__ __align__(128) __half g_Wp[(size_t)3072 * KW];               // perm [row][k]
__device__ __align__(128) __half g_xbk[(size_t)T_STEPS * BATCH * XST];  // [t][b][k]
__device__ __align__(128) __half g_hbk[2 * BATCH * HID];                // ping-pong [b][k]
__device__ __align__(128) float  g_hist[(size_t)DEC_T * HID * BATCH];   // [t'][k][b] fp32
__device__ float    g_bias[3072];
__device__ float    g_WdecT[HID * OUTD];
__device__ unsigned g_barcnt;
__device__ unsigned g_bargen;

// ---------------- helpers ----------------
__device__ __forceinline__ uint32_t smem_u32(const void* p) {
    uint32_t a;
    asm("{ .reg .u64 t; cvta.to.shared.u64 t, %1; cvt.u32.u64 %0, t; }" : "=r"(a) : "l"(p));
    return a;
}
__device__ __forceinline__ void cp16(uint32_t dst, const void* src) {
    asm volatile("cp.async.cg.shared.global [%0], [%1], 16;" :: "r"(dst), "l"(src));
}
__device__ __forceinline__ void cpcommit() { asm volatile("cp.async.commit_group;" ::: "memory"); }
template <int N> __device__ __forceinline__ void cpwait() {
    asm volatile("cp.async.wait_group %0;" :: "n"(N) : "memory");
}
__device__ __forceinline__ void mma16(float* d, const uint32_t* a, const uint32_t* b) {
    asm volatile("mma.sync.aligned.m16n8k16.row.col.f32.f16.f16.f32 "
        "{%0,%1,%2,%3}, {%4,%5,%6,%7}, {%8,%9}, {%0,%1,%2,%3};"
        : "+f"(d[0]), "+f"(d[1]), "+f"(d[2]), "+f"(d[3])
        : "r"(a[0]), "r"(a[1]), "r"(a[2]), "r"(a[3]), "r"(b[0]), "r"(b[1]));
}
__device__ __forceinline__ float sigm(float x)  { return __fdividef(1.f, 1.f + __expf(-x)); }
__device__ __forceinline__ float tanhx(float x) { return __fdividef(2.f, 1.f + __expf(-2.f * x)) - 1.f; }

// ---------------- grid barrier (96 CTAs, all resident at 1/SM) ----------------
__device__ __forceinline__ void gridbar() {
    __syncthreads();
    if (threadIdx.x == 0) {
        __threadfence();
        unsigned gen = *(volatile unsigned*)&g_bargen;
        if (atomicAdd(&g_barcnt, 1u) == NCTA - 1u) {
            atomicExch(&g_barcnt, 0u);
            __threadfence();
            atomicAdd(&g_bargen, 1u);
        } else {
            while (*(volatile unsigned*)&g_bargen == gen) { }
        }
        __threadfence();
    }
    __syncthreads();
}

// ---------------- prep kernels ----------------
// perm row p = nTile*64 + wn*32 + nt*8 + rlk*2 + e  ->  orig gate(nt)*768 + unit
// unit = nTile*16 + wn*8 + rlk*2 + e
__global__ void prep_w_kernel(const float* __restrict__ Wih, const float* __restrict__ Whh,
                              const float* __restrict__ bih, const float* __restrict__ bhh) {
    int idx = blockIdx.x * blockDim.x + threadIdx.x;
    if (idx < 3072) {
        int nTile = idx >> 6, j = idx & 63;
        int wn = j >> 5, jj = j & 31, nt = jj >> 3, w3 = jj & 7;
        int unit = nTile * 16 + wn * 8 + w3;
        int orig = nt * HID + unit;
        g_bias[idx] = bih[orig] + bhh[orig];
    }
    for (size_t ee = idx; ee < (size_t)3072 * KW; ee += (size_t)gridDim.x * blockDim.x) {
        int p = (int)(ee / KW), k = (int)(ee % KW);
        int nTile = p >> 6, j = p & 63;
        int wn = j >> 5, jj = j & 31, nt = jj >> 3, w3 = jj & 7;
        int unit = nTile * 16 + wn * 8 + w3;
        int orig = nt * HID + unit;
        float v = 0.f;
        if (k < HID)                v = Whh[(size_t)orig * HID + k];
        else if (k < HID + IN_DIMV) v = Wih[(size_t)orig * IN_DIMV + (k - HID)];
        g_Wp[ee] = __float2half_rn(v);
    }
}
__global__ void prep_x_kernel(const float* __restrict__ seq) {
    for (size_t e = blockIdx.x * blockDim.x + threadIdx.x;
         e < (size_t)T_STEPS * BATCH * XST; e += (size_t)gridDim.x * blockDim.x) {
        int k = (int)(e % XST);
        size_t tb = e / XST;
        g_xbk[e] = (k < IN_DIMV) ? __float2half_rn(seq[tb * IN_DIMV + k]) : __ushort_as_half(0);
    }
}
__global__ void zero_h_kernel() {
    int i = blockIdx.x * blockDim.x + threadIdx.x;
    if (i < 2 * BATCH * HID) g_hbk[i] = __ushort_as_half(0);
}
__global__ void transpose_wdec_kernel(const float* __restrict__ Wdec) {
    __shared__ float tile[32][33];
    int k0 = blockIdx.x * 32, o0 = blockIdx.y * 32;
    int tx = threadIdx.x, ty = threadIdx.y;
    #pragma unroll
    for (int i = 0; i < 32; i += 8)
        tile[ty + i][tx] = Wdec[(size_t)(o0 + ty + i) * HID + k0 + tx];
    __syncthreads();
    #pragma unroll
    for (int i = 0; i < 32; i += 8)
        g_WdecT[(size_t)(k0 + ty + i) * OUTD + o0 + tx] = tile[tx][ty + i];
}

// ---------------- persistent fp16 tensor-core LSTM (register cell state) ----
__global__ void __launch_bounds__(256, 1) lstm_mma_kernel() {
    extern __shared__ char smc[];
    __half* sW  = (__half*)smc;                       // [64][WST]
    __half* sHX = (__half*)(smc + SM_W_BYTES);        // NSTG x [128][AST]
    const uint32_t sHXu = smem_u32(sHX);

    const int tid = threadIdx.x, lane = tid & 31, wid = tid >> 5;
    const int wm = wid & 3, wn = wid >> 2;            // warp grid 4(batch) x 2(rows)
    const int cta = blockIdx.x, nTile = cta >> 1, bHalf = cta & 1;
    const int q = lane >> 2, rlk = lane & 3;
    const int ku0 = nTile * 16 + wn * 8 + rlk * 2;

    // stage W tile (restride 960 -> 968, conflict-free) once
    for (int i = tid; i < 64 * 120; i += 256) {
        int r = i / 120, s = i % 120;
        *(uint4*)(sW + r * WST + s * 8) =
            *(const uint4*)(g_Wp + (size_t)(nTile * 64 + r) * KW + s * 8);
    }

    float bias_r[4][2];
    #pragma unroll
    for (int nt = 0; nt < 4; nt++)
        #pragma unroll
        for (int e = 0; e < 2; e++)
            bias_r[nt][e] = g_bias[nTile * 64 + wn * 32 + nt * 8 + rlk * 2 + e];

    float cst[8];
    #pragma unroll
    for (int i = 0; i < 8; i++) cst[i] = 0.f;

    int rowS[4], segS[4];
    #pragma unroll
    for (int i = 0; i < 4; i++) { int s = i * 256 + tid; rowS[i] = s >> 3; segS[i] = s & 7; }

    __syncthreads();

    for (int t = 0; t < T_STEPS; t++) {
        const int rslot = t & 1, wslot = rslot ^ 1;

        auto issue = [&](int c) {
            const uint32_t dst = sHXu + (c & 3) * SM_HX_STAGE;
            if (c < 12) {
                const __half* src = g_hbk + ((size_t)(rslot * BATCH + bHalf * 128)) * HID + c * 64;
                #pragma unroll
                for (int i = 0; i < 4; i++)
                    cp16(dst + (rowS[i] * AST + segS[i] * 8) * 2,
                         src + (size_t)rowS[i] * HID + segS[i] * 8);
            } else {
                const __half* src = g_xbk + ((size_t)t * BATCH + bHalf * 128) * XST + (c - 12) * 64;
                #pragma unroll
                for (int i = 0; i < 4; i++)
                    cp16(dst + (rowS[i] * AST + segS[i] * 8) * 2,
                         src + (size_t)rowS[i] * XST + segS[i] * 8);
            }
            cpcommit();
        };

        float d[2][4][4];
        #pragma unroll
        for (int mt = 0; mt < 2; mt++)
            #pragma unroll
            for (int nt = 0; nt < 4; nt++)
                #pragma unroll
                for (int j = 0; j < 4; j++) d[mt][nt][j] = 0.f;

        issue(0); issue(1); issue(2);

        for (int c = 0; c < NCHK; c++) {
            if (c < NCHK - 2)       cpwait<2>();
            else if (c == NCHK - 2) cpwait<1>();
            else                    cpwait<0>();
            __syncthreads();
            if (c + 3 < NCHK) issue(c + 3);

            const __half* A = sHX + (c & 3) * (128 * AST);
            #pragma unroll
            for (int ks = 0; ks < 4; ks++) {
                const int kb = ks * 16;
                const int kw = c * 64 + kb;
                uint32_t a[2][4], b[4][2];
                #pragma unroll
                for (int mt = 0; mt < 2; mt++) {
                    const int m0 = wm * 32 + mt * 16 + q;
                    a[mt][0] = *(const uint32_t*)(A + (m0)     * AST + kb + 2 * rlk);
                    a[mt][1] = *(const uint32_t*)(A + (m0 + 8) * AST + kb + 2 * rlk);
                    a[mt][2] = *(const uint32_t*)(A + (m0)     * AST + kb + 2 * rlk + 8);
                    a[mt][3] = *(const uint32_t*)(A + (m0 + 8) * AST + kb + 2 * rlk + 8);
                }
                #pragma unroll
                for (int nt = 0; nt < 4; nt++) {
                    const int n0 = wn * 32 + nt * 8 + q;
                    b[nt][0] = *(const uint32_t*)(sW + n0 * WST + kw + 2 * rlk);
                    b[nt][1] = *(const uint32_t*)(sW + n0 * WST + kw + 2 * rlk + 8);
                }
                #pragma unroll
                for (int mt = 0; mt < 2; mt++)
                    #pragma unroll
                    for (int nt = 0; nt < 4; nt++)
                        mma16(d[mt][nt], a[mt], b[nt]);
            }
        }

        // register-resident epilogue: all 4 gates of this thread's units are local
        #pragma unroll
        for (int mt = 0; mt < 2; mt++) {
            #pragma unroll
            for (int h = 0; h < 2; h++) {
                float ho[2];
                #pragma unroll
                for (int e = 0; e < 2; e++) {
                    float xi = d[mt][0][2 * h + e] + bias_r[0][e];
                    float xf = d[mt][1][2 * h + e] + bias_r[1][e];
                    float xg = d[mt][2][2 * h + e] + bias_r[2][e];
                    float xo = d[mt][3][2 * h + e] + bias_r[3][e];
                    const int ci = mt * 4 + h * 2 + e;
                    float cv = fmaf(sigm(xf), cst[ci], sigm(xi) * tanhx(xg));
                    cst[ci] = cv;
                    ho[e] = sigm(xo) * tanhx(cv);
                }
                const int bb = bHalf * 128 + wm * 32 + mt * 16 + q + 8 * h;
                *(__half2*)(g_hbk + ((size_t)wslot * BATCH + bb) * HID + ku0) =
                    __floats2half2_rn(ho[0], ho[1]);
                if (t >= DEC_T) {
                    const size_t hb = (size_t)(t - DEC_T) * (HID * BATCH);
                    g_hist[hb + (size_t)(ku0)     * BATCH + bb] = ho[0];
                    g_hist[hb + (size_t)(ku0 + 1) * BATCH + bb] = ho[1];
                }
            }
        }
        gridbar();
    }
}

// ---------------- decoder GEMM: out[t][b][o] ----------------
__global__ void __launch_bounds__(256)
decode_kernel(const float* __restrict__ bdec, float* __restrict__ out) {
    __shared__ float wt[KTILE * 32];
    const int og = blockIdx.x, t = blockIdx.y, tid = threadIdx.x;
    float acc[32];
    #pragma unroll
    for (int i = 0; i < 32; i++) acc[i] = 0.f;
    for (int kt = 0; kt < HID / KTILE; kt++) {
        const int k0 = kt * KTILE;
        #pragma unroll
        for (int i = 0; i < 4; i++) {
            int e = i * 256 + tid, kk = e >> 5, oo = e & 31;
            wt[e] = g_WdecT[(size_t)(k0 + kk) * OUTD + og * 32 + oo];
        }
        __syncthreads();
        #pragma unroll 8
        for (int kk = 0; kk < KTILE; kk++) {
            float hv = g_hist[((size_t)t * HID + k0 + kk) * BATCH + tid];
            #pragma unroll
            for (int o4 = 0; o4 < 8; o4++) {
                float4 w = *(const float4*)&wt[kk * 32 + o4 * 4];
                acc[o4 * 4 + 0] += hv * w.x;  acc[o4 * 4 + 1] += hv * w.y;
                acc[o4 * 4 + 2] += hv * w.z;  acc[o4 * 4 + 3] += hv * w.w;
            }
        }
        __syncthreads();
    }
    size_t ob = ((size_t)t * BATCH + tid) * OUTD + og * 32;
    #pragma unroll
    for (int o4 = 0; o4 < 8; o4++) {
        float4 r;
        r.x = acc[o4 * 4 + 0] + bdec[og * 32 + o4 * 4 + 0];
        r.y = acc[o4 * 4 + 1] + bdec[og * 32 + o4 * 4 + 1];
        r.z = acc[o4 * 4 + 2] + bdec[og * 32 + o4 * 4 + 2];
        r.w = acc[o4 * 4 + 3] + bdec[og * 32 + o4 * 4 + 3];
        *(float4*)&out[ob + o4 * 4] = r;
    }
}

// ---------------- launch ----------------
extern "C" void kernel_launch(void* const* d_in, const int* in_sizes, int n_in,
                              void* d_out, int out_size) {
    const float* seq  = (const float*)d_in[0];
    const float* Wih  = (const float*)d_in[1];
    const float* Whh  = (const float*)d_in[2];
    const float* bih  = (const float*)d_in[3];
    const float* bhh  = (const float*)d_in[4];
    const float* Wdec = (const float*)d_in[5];
    const float* bdec = (const float*)d_in[6];
    float* out = (float*)d_out;

    cudaFuncSetAttribute(lstm_mma_kernel, cudaFuncAttributeMaxDynamicSharedMemorySize, SMEM_SZ);

    zero_h_kernel<<<(2 * BATCH * HID + 255) / 256, 256>>>();
    prep_w_kernel<<<512, 256>>>(Wih, Whh, bih, bhh);
    prep_x_kernel<<<2048, 256>>>(seq);
    dim3 tb(32, 8);
    transpose_wdec_kernel<<<dim3(HID / 32, OUTD / 32), tb>>>(Wdec);
    lstm_mma_kernel<<<NCTA, 256, SMEM_SZ>>>();
    decode_kernel<<<dim3(4, DEC_T), 256>>>(bdec, out);
}

// round 8
// speedup vs baseline: 7.6318x; 1.0179x over previous
#include <cuda_runtime.h>
#include <cuda_fp16.h>
#include <cstdint>
#include <math.h>

#define T_STEPS 512
#define BATCH   256
#define IN_DIMV 129
#define HID     768
#define OUTD    128
#define XST     192
#define CHUNK   128
#define NCHK    6              // 768 / 128
#define NCTA    96             // 48 row tiles x 2 batch halves
#define DEC_T   256
#define KTILE   32

#define AST 136                // hx stage row stride (halves)
#define WST 776                // W smem row stride (halves)
#define WXS 216                // xproj W smem stride (halves)
#define STAGE_B 34816          // 128*136*2
#define SM_W_B  99328          // 64*776*2
#define SMEM_SZ (SM_W_B + 3 * STAGE_B)   // 203776

// ---------------- static device scratch ----------------
__device__ __align__(128) __half g_Wp [(size_t)3072 * HID];             // perm [row][k<768]
__device__ __align__(128) __half g_Wxp[(size_t)3072 * XST];             // perm [row][k xpart]
__device__ __align__(128) __half g_xbk[(size_t)T_STEPS * BATCH * XST];  // [t][b][k]
__device__ __align__(128) float  g_xp [(size_t)T_STEPS * 48 * 64 * 256];// [t][tile][col64][b256]
__device__ __align__(128) __half g_hbk[2 * BATCH * HID];                // ping-pong [b][k]
__device__ __align__(128) float  g_hist[(size_t)DEC_T * HID * BATCH];   // [t'][k][b] fp32
__device__ float    g_bias[3072];
__device__ float    g_WdecT[HID * OUTD];
__device__ unsigned g_barcnt;
__device__ unsigned g_bargen;

// ---------------- helpers ----------------
__device__ __forceinline__ uint32_t smem_u32(const void* p) {
    uint32_t a;
    asm("{ .reg .u64 t; cvta.to.shared.u64 t, %1; cvt.u32.u64 %0, t; }" : "=r"(a) : "l"(p));
    return a;
}
__device__ __forceinline__ void cp16(uint32_t dst, const void* src) {
    asm volatile("cp.async.cg.shared.global [%0], [%1], 16;" :: "r"(dst), "l"(src));
}
__device__ __forceinline__ void cpcommit() { asm volatile("cp.async.commit_group;" ::: "memory"); }
template <int N> __device__ __forceinline__ void cpwait() {
    asm volatile("cp.async.wait_group %0;" :: "n"(N) : "memory");
}
#define LDSM4(r0, r1, r2, r3, addr) \
    asm volatile("ldmatrix.sync.aligned.m8n8.x4.shared.b16 {%0,%1,%2,%3}, [%4];" \
        : "=r"(r0), "=r"(r1), "=r"(r2), "=r"(r3) : "r"(addr))
__device__ __forceinline__ void mma16(float* d, const uint32_t* a, const uint32_t* b) {
    asm volatile("mma.sync.aligned.m16n8k16.row.col.f32.f16.f16.f32 "
        "{%0,%1,%2,%3}, {%4,%5,%6,%7}, {%8,%9}, {%0,%1,%2,%3};"
        : "+f"(d[0]), "+f"(d[1]), "+f"(d[2]), "+f"(d[3])
        : "r"(a[0]), "r"(a[1]), "r"(a[2]), "r"(a[3]), "r"(b[0]), "r"(b[1]));
}
__device__ __forceinline__ float tanha(float x) {
    float y; asm("tanh.approx.f32 %0, %1;" : "=f"(y) : "f"(x)); return y;
}
__device__ __forceinline__ float sigm(float x) { return fmaf(0.5f, tanha(0.5f * x), 0.5f); }

// ---------------- grid barrier (96 CTAs, all resident at 1/SM) ----------------
__device__ __forceinline__ void gridbar() {
    __syncthreads();
    if (threadIdx.x == 0) {
        __threadfence();
        unsigned gen = *(volatile unsigned*)&g_bargen;
        if (atomicAdd(&g_barcnt, 1u) == NCTA - 1u) {
            atomicExch(&g_barcnt, 0u);
            __threadfence();
            atomicAdd(&g_bargen, 1u);
        } else {
            while (*(volatile unsigned*)&g_bargen == gen) { }
        }
        __threadfence();
    }
    __syncthreads();
}

// ---------------- prep kernels ----------------
// perm row p = nTile*64 + wn*32 + nt*8 + w3  ->  orig gate(nt)*768 + unit
__global__ void prep_w_kernel(const float* __restrict__ Wih, const float* __restrict__ Whh,
                              const float* __restrict__ bih, const float* __restrict__ bhh) {
    int idx = blockIdx.x * blockDim.x + threadIdx.x;
    if (idx < 3072) {
        int nTile = idx >> 6, j = idx & 63;
        int wn = j >> 5, jj = j & 31, nt = jj >> 3, w3 = jj & 7;
        int orig = nt * HID + nTile * 16 + wn * 8 + w3;
        g_bias[idx] = bih[orig] + bhh[orig];
    }
    for (size_t ee = idx; ee < (size_t)3072 * HID; ee += (size_t)gridDim.x * blockDim.x) {
        int p = (int)(ee / HID), k = (int)(ee % HID);
        int nTile = p >> 6, j = p & 63;
        int wn = j >> 5, jj = j & 31, nt = jj >> 3, w3 = jj & 7;
        int orig = nt * HID + nTile * 16 + wn * 8 + w3;
        g_Wp[ee] = __float2half_rn(Whh[(size_t)orig * HID + k]);
    }
    for (size_t ee = idx; ee < (size_t)3072 * XST; ee += (size_t)gridDim.x * blockDim.x) {
        int p = (int)(ee / XST), k = (int)(ee % XST);
        int nTile = p >> 6, j = p & 63;
        int wn = j >> 5, jj = j & 31, nt = jj >> 3, w3 = jj & 7;
        int orig = nt * HID + nTile * 16 + wn * 8 + w3;
        g_Wxp[ee] = (k < IN_DIMV) ? __float2half_rn(Wih[(size_t)orig * IN_DIMV + k])
                                  : __ushort_as_half(0);
    }
}
__global__ void prep_x_kernel(const float* __restrict__ seq) {
    for (size_t e = blockIdx.x * blockDim.x + threadIdx.x;
         e < (size_t)T_STEPS * BATCH * XST; e += (size_t)gridDim.x * blockDim.x) {
        int k = (int)(e % XST);
        size_t tb = e / XST;
        g_xbk[e] = (k < IN_DIMV) ? __float2half_rn(seq[tb * IN_DIMV + k]) : __ushort_as_half(0);
    }
}
__global__ void zero_h_kernel() {
    int i = blockIdx.x * blockDim.x + threadIdx.x;
    if (i < 2 * BATCH * HID) g_hbk[i] = __ushort_as_half(0);
}
__global__ void transpose_wdec_kernel(const float* __restrict__ Wdec) {
    __shared__ float tile[32][33];
    int k0 = blockIdx.x * 32, o0 = blockIdx.y * 32;
    int tx = threadIdx.x, ty = threadIdx.y;
    #pragma unroll
    for (int i = 0; i < 32; i += 8)
        tile[ty + i][tx] = Wdec[(size_t)(o0 + ty + i) * HID + k0 + tx];
    __syncthreads();
    #pragma unroll
    for (int i = 0; i < 32; i += 8)
        g_WdecT[(size_t)(k0 + ty + i) * OUTD + o0 + tx] = tile[tx][ty + i];
}

// ---------------- xproj GEMM: g_xp = Wx * x for all t ----------------
__global__ void __launch_bounds__(256) xproj_kernel() {
    __shared__ __half sX[128 * 72];
    __shared__ __half sWx[64 * WXS];
    const int tid = threadIdx.x, lane = tid & 31, wid = tid >> 5;
    const int wm = wid & 3, wn = wid >> 2;
    const int tile = blockIdx.x >> 1, bHalf = blockIdx.x & 1, t = blockIdx.y;
    const int q = lane >> 2, rlk = lane & 3;

    for (int i = tid; i < 64 * 24; i += 256) {
        int r = i / 24, s = i % 24;
        *(uint4*)(sWx + r * WXS + s * 8) =
            *(const uint4*)(g_Wxp + (size_t)(tile * 64 + r) * XST + s * 8);
    }

    float d[2][4][4];
    #pragma unroll
    for (int mt = 0; mt < 2; mt++)
        #pragma unroll
        for (int nt = 0; nt < 4; nt++)
            #pragma unroll
            for (int j = 0; j < 4; j++) d[mt][nt][j] = 0.f;

    for (int c = 0; c < 3; c++) {
        __syncthreads();
        #pragma unroll
        for (int j = 0; j < 4; j++) {
            int s = j * 256 + tid, row = s >> 3, seg = s & 7;
            *(uint4*)(sX + row * 72 + seg * 8) =
                *(const uint4*)(g_xbk + ((size_t)t * BATCH + bHalf * 128 + row) * XST
                                + c * 64 + seg * 8);
        }
        __syncthreads();
        #pragma unroll
        for (int ks = 0; ks < 4; ks++) {
            const int kb = ks * 16, kw = c * 64 + kb;
            uint32_t a[2][4], b[4][2];
            #pragma unroll
            for (int mt = 0; mt < 2; mt++) {
                const int m0 = wm * 32 + mt * 16 + q;
                a[mt][0] = *(const uint32_t*)(sX + (m0)     * 72 + kb + 2 * rlk);
                a[mt][1] = *(const uint32_t*)(sX + (m0 + 8) * 72 + kb + 2 * rlk);
                a[mt][2] = *(const uint32_t*)(sX + (m0)     * 72 + kb + 2 * rlk + 8);
                a[mt][3] = *(const uint32_t*)(sX + (m0 + 8) * 72 + kb + 2 * rlk + 8);
            }
            #pragma unroll
            for (int nt = 0; nt < 4; nt++) {
                const int n0 = wn * 32 + nt * 8 + q;
                b[nt][0] = *(const uint32_t*)(sWx + n0 * WXS + kw + 2 * rlk);
                b[nt][1] = *(const uint32_t*)(sWx + n0 * WXS + kw + 2 * rlk + 8);
            }
            #pragma unroll
            for (int mt = 0; mt < 2; mt++)
                #pragma unroll
                for (int nt = 0; nt < 4; nt++)
                    mma16(d[mt][nt], a[mt], b[nt]);
        }
    }

    const size_t xb = ((size_t)t * 48 + tile) * 16384;
    #pragma unroll
    for (int mt = 0; mt < 2; mt++)
        #pragma unroll
        for (int nt = 0; nt < 4; nt++)
            #pragma unroll
            for (int j = 0; j < 4; j++) {
                int col = wn * 32 + nt * 8 + 2 * rlk + (j & 1);
                int bb  = bHalf * 128 + wm * 32 + mt * 16 + q + 8 * (j >> 1);
                g_xp[xb + (size_t)col * 256 + bb] = d[mt][nt][j];
            }
}

// ---------------- persistent fp16 tensor-core LSTM ----------------
__global__ void __launch_bounds__(256, 1) lstm_mma_kernel() {
    extern __shared__ char smc[];
    __half* sW = (__half*)smc;                      // [64][776]
    const uint32_t sWu  = smem_u32(smc);
    const uint32_t sStU = sWu + SM_W_B;

    const int tid = threadIdx.x, lane = tid & 31, wid = tid >> 5;
    const int wm = wid & 3, wn = wid >> 2;          // 4 batch-warps x 2 row-warps
    const int cta = blockIdx.x, nTile = cta >> 1, bHalf = cta & 1;
    const int q = lane >> 2, rlk = lane & 3;
    const int ku0 = nTile * 16 + wn * 8 + rlk * 2;

    // resident W tile (768 -> 776 restride)
    for (int i = tid; i < 64 * 96; i += 256) {
        int r = i / 96, s = i % 96;
        *(uint4*)(sW + r * WST + s * 8) =
            *(const uint4*)(g_Wp + (size_t)(nTile * 64 + r) * HID + s * 8);
    }

    float bias_r[4][2];
    #pragma unroll
    for (int nt = 0; nt < 4; nt++)
        #pragma unroll
        for (int e = 0; e < 2; e++)
            bias_r[nt][e] = g_bias[nTile * 64 + wn * 32 + nt * 8 + rlk * 2 + e];

    float cst[8];
    #pragma unroll
    for (int i = 0; i < 8; i++) cst[i] = 0.f;

    // cp.async indices: 8 x 16B per thread per chunk
    const int cprow0 = tid >> 4, cpseg = tid & 15;
    // ldmatrix per-lane byte offsets
    const int la = lane;
    const uint32_t offA0 = ((wm * 32 + (la & 7) + ((la >> 3) & 1) * 8) * AST
                            + ((la >> 4) & 1) * 8) * 2;
    const uint32_t offA1 = offA0 + 16 * AST * 2;
    const uint32_t offB0 = sWu + ((wn * 32 + (la & 7) + ((la >> 4) & 1) * 8) * WST
                            + ((la >> 3) & 1) * 8) * 2;
    const uint32_t offB1 = offB0 + 16 * WST * 2;

    float d[2][4][4];
    auto load_xp = [&](int tt) {
        const float* xp = g_xp + ((size_t)tt * 48 + nTile) * 16384;
        #pragma unroll
        for (int mt = 0; mt < 2; mt++)
            #pragma unroll
            for (int nt = 0; nt < 4; nt++)
                #pragma unroll
                for (int j = 0; j < 4; j++) {
                    int col = wn * 32 + nt * 8 + 2 * rlk + (j & 1);
                    int bb  = bHalf * 128 + wm * 32 + mt * 16 + q + 8 * (j >> 1);
                    d[mt][nt][j] = __ldg(xp + (size_t)col * 256 + bb);
                }
    };

    __syncthreads();
    load_xp(0);

    for (int t = 0; t < T_STEPS; t++) {
        const int rslot = t & 1, wslot = rslot ^ 1;
        const __half* hsrc = g_hbk + (size_t)(rslot * BATCH + bHalf * 128) * HID;

        auto issue = [&](int c) {
            const uint32_t dst0 = sStU + (c % 3) * STAGE_B;
            const __half* src = hsrc + c * CHUNK;
            #pragma unroll
            for (int j = 0; j < 8; j++) {
                int row = j * 16 + cprow0;
                cp16(dst0 + (row * AST + cpseg * 8) * 2, src + (size_t)row * HID + cpseg * 8);
            }
            cpcommit();
        };

        issue(0); issue(1);
        for (int c = 0; c < NCHK; c++) {
            if (c < NCHK - 1) cpwait<1>(); else cpwait<0>();
            __syncthreads();
            if (c + 2 < NCHK) issue(c + 2);

            const uint32_t sb = sStU + (c % 3) * STAGE_B;
            const uint32_t wb = c * (CHUNK * 2);
            #pragma unroll
            for (int ks = 0; ks < 8; ks++) {
                uint32_t a[2][4], b[4][2];
                LDSM4(a[0][0], a[0][1], a[0][2], a[0][3], sb + offA0 + ks * 32);
                LDSM4(a[1][0], a[1][1], a[1][2], a[1][3], sb + offA1 + ks * 32);
                LDSM4(b[0][0], b[0][1], b[1][0], b[1][1], offB0 + wb + ks * 32);
                LDSM4(b[2][0], b[2][1], b[3][0], b[3][1], offB1 + wb + ks * 32);
                #pragma unroll
                for (int mt = 0; mt < 2; mt++)
                    #pragma unroll
                    for (int nt = 0; nt < 4; nt++)
                        mma16(d[mt][nt], a[mt], b[nt]);
            }
        }

        // register-resident epilogue
        #pragma unroll
        for (int mt = 0; mt < 2; mt++) {
            #pragma unroll
            for (int h = 0; h < 2; h++) {
                float ho[2];
                #pragma unroll
                for (int e = 0; e < 2; e++) {
                    float xi = d[mt][0][2 * h + e] + bias_r[0][e];
                    float xf = d[mt][1][2 * h + e] + bias_r[1][e];
                    float xg = d[mt][2][2 * h + e] + bias_r[2][e];
                    float xo = d[mt][3][2 * h + e] + bias_r[3][e];
                    const int ci = mt * 4 + h * 2 + e;
                    float cv = fmaf(sigm(xf), cst[ci], sigm(xi) * tanha(xg));
                    cst[ci] = cv;
                    ho[e] = sigm(xo) * tanha(cv);
                }
                const int bb = bHalf * 128 + wm * 32 + mt * 16 + q + 8 * h;
                *(__half2*)(g_hbk + ((size_t)wslot * BATCH + bb) * HID + ku0) =
                    __floats2half2_rn(ho[0], ho[1]);
                if (t >= DEC_T) {
                    const size_t hb = (size_t)(t - DEC_T) * (HID * BATCH);
                    g_hist[hb + (size_t)(ku0)     * BATCH + bb] = ho[0];
                    g_hist[hb + (size_t)(ku0 + 1) * BATCH + bb] = ho[1];
                }
            }
        }
        if (t + 1 < T_STEPS) load_xp(t + 1);   // hidden behind gridbar
        gridbar();
    }
}

// ---------------- decoder GEMM: out[t][b][o] ----------------
__global__ void __launch_bounds__(256)
decode_kernel(const float* __restrict__ bdec, float* __restrict__ out) {
    __shared__ float wt[KTILE * 32];
    const int og = blockIdx.x, t = blockIdx.y, tid = threadIdx.x;
    float acc[32];
    #pragma unroll
    for (int i = 0; i < 32; i++) acc[i] = 0.f;
    for (int kt = 0; kt < HID / KTILE; kt++) {
        const int k0 = kt * KTILE;
        #pragma unroll
        for (int i = 0; i < 4; i++) {
            int e = i * 256 + tid, kk = e >> 5, oo = e & 31;
            wt[e] = g_WdecT[(size_t)(k0 + kk) * OUTD + og * 32 + oo];
        }
        __syncthreads();
        #pragma unroll 8
        for (int kk = 0; kk < KTILE; kk++) {
            float hv = g_hist[((size_t)t * HID + k0 + kk) * BATCH + tid];
            #pragma unroll
            for (int o4 = 0; o4 < 8; o4++) {
                float4 w = *(const float4*)&wt[kk * 32 + o4 * 4];
                acc[o4 * 4 + 0] += hv * w.x;  acc[o4 * 4 + 1] += hv * w.y;
                acc[o4 * 4 + 2] += hv * w.z;  acc[o4 * 4 + 3] += hv * w.w;
            }
        }
        __syncthreads();
    }
    size_t ob = ((size_t)t * BATCH + tid) * OUTD + og * 32;
    #pragma unroll
    for (int o4 = 0; o4 < 8; o4++) {
        float4 r;
        r.x = acc[o4 * 4 + 0] + bdec[og * 32 + o4 * 4 + 0];
        r.y = acc[o4 * 4 + 1] + bdec[og * 32 + o4 * 4 + 1];
        r.z = acc[o4 * 4 + 2] + bdec[og * 32 + o4 * 4 + 2];
        r.w = acc[o4 * 4 + 3] + bdec[og * 32 + o4 * 4 + 3];
        *(float4*)&out[ob + o4 * 4] = r;
    }
}

// ---------------- launch ----------------
extern "C" void kernel_launch(void* const* d_in, const int* in_sizes, int n_in,
                              void* d_out, int out_size) {
    const float* seq  = (const float*)d_in[0];
    const float* Wih  = (const float*)d_in[1];
    const float* Whh  = (const float*)d_in[2];
    const float* bih  = (const float*)d_in[3];
    const float* bhh  = (const float*)d_in[4];
    const float* Wdec = (const float*)d_in[5];
    const float* bdec = (const float*)d_in[6];
    float* out = (float*)d_out;

    cudaFuncSetAttribute(lstm_mma_kernel, cudaFuncAttributeMaxDynamicSharedMemorySize, SMEM_SZ);

    zero_h_kernel<<<(2 * BATCH * HID + 255) / 256, 256>>>();
    prep_w_kernel<<<512, 256>>>(Wih, Whh, bih, bhh);
    prep_x_kernel<<<2048, 256>>>(seq);
    dim3 tb(32, 8);
    transpose_wdec_kernel<<<dim3(HID / 32, OUTD / 32), tb>>>(Wdec);
    xproj_kernel<<<dim3(96, T_STEPS), 256>>>();
    lstm_mma_kernel<<<NCTA, 256, SMEM_SZ>>>();
    decode_kernel<<<dim3(4, DEC_T), 256>>>(bdec, out);
}